// round 3
// baseline (speedup 1.0000x reference)
#include <cuda_runtime.h>
#include <math.h>

#define B_ROWS 4096
#define KTOK   64
#define DM     256
#define DDYN   512
#define NH     4
#define SCALE  0.125f
#define LN_EPS 1e-5f
#define WT_STRIDE 260   // padded smem stride for weight tiles
#define AST       260   // padded smem stride for activation tiles

// ---- scratch (allocation-free rule: __device__ globals) ----
__device__ float g_h0 [B_ROWS * DM];        // 4 MB
__device__ float g_u  [B_ROWS * DM * NH];   // 16 MB : u[b][j][h]
__device__ float g_qbk[B_ROWS * NH];        // 64 KB

// ============================================================
// Shared-memory tiled GEMM: C[rows,256] = Asm[rows,kdim] @ Wg[kdim,256]
// Thread tile 4 tokens x 8 cols. rows = 4 * (blockDim/32).
// Weight rows streamed through 16x256 smem tile (padded stride).
// ============================================================
template<int NTHREADS>
__device__ __forceinline__ void gemm_acc(
    const float* __restrict__ Asm, int astride, int kdim,
    const float* __restrict__ Wg, float* __restrict__ Wt,
    float acc[4][8], int tid)
{
#pragma unroll
    for (int t = 0; t < 4; t++)
#pragma unroll
        for (int j = 0; j < 8; j++) acc[t][j] = 0.f;

    const int tc   = tid & 31;
    const int tok0 = (tid >> 5) * 4;
    const int col0 = tc * 8;
    const int nkt  = kdim >> 4;

    for (int kt = 0; kt < nkt; ++kt) {
        // stage 16 weight rows (16x256 floats) into smem, coalesced
        const float4* src = reinterpret_cast<const float4*>(Wg + kt * 16 * DM);
#pragma unroll
        for (int f = tid; f < 1024; f += NTHREADS) {
            int row = f >> 6, c4 = f & 63;
            float4 v = src[f];
            *reinterpret_cast<float4*>(Wt + row * WT_STRIDE + c4 * 4) = v;
        }
        __syncthreads();
#pragma unroll
        for (int kk4 = 0; kk4 < 4; ++kk4) {
            const int kbase = kt * 16 + kk4 * 4;
            float a_[4][4];
#pragma unroll
            for (int t = 0; t < 4; t++) {
                float4 v = *reinterpret_cast<const float4*>(Asm + (tok0 + t) * astride + kbase);
                a_[t][0] = v.x; a_[t][1] = v.y; a_[t][2] = v.z; a_[t][3] = v.w;
            }
#pragma unroll
            for (int r = 0; r < 4; r++) {
                const float4 w0 = *reinterpret_cast<const float4*>(Wt + (kk4 * 4 + r) * WT_STRIDE + col0);
                const float4 w1 = *reinterpret_cast<const float4*>(Wt + (kk4 * 4 + r) * WT_STRIDE + col0 + 4);
                float w[8] = {w0.x, w0.y, w0.z, w0.w, w1.x, w1.y, w1.z, w1.w};
#pragma unroll
                for (int t = 0; t < 4; t++) {
                    const float a = a_[t][r];
#pragma unroll
                    for (int j = 0; j < 8; j++)
                        acc[t][j] = fmaf(a, w[j], acc[t][j]);
                }
            }
        }
        __syncthreads();
    }
}

// epilogue: add bias, LayerNorm per token row, write to smem (strided)
__device__ __forceinline__ void epi_ln(
    float acc[4][8], const float* __restrict__ bias,
    const float* __restrict__ g, const float* __restrict__ bn,
    float* __restrict__ out, int ostride, int tid)
{
    const int tc = tid & 31, tok0 = (tid >> 5) * 4, col0 = tc * 8;
#pragma unroll
    for (int t = 0; t < 4; t++) {
        float s = 0.f, s2 = 0.f;
#pragma unroll
        for (int j = 0; j < 8; j++) {
            float v = acc[t][j] + bias[col0 + j];
            acc[t][j] = v; s += v; s2 += v * v;
        }
#pragma unroll
        for (int off = 16; off; off >>= 1) {
            s  += __shfl_xor_sync(0xffffffffu, s,  off);
            s2 += __shfl_xor_sync(0xffffffffu, s2, off);
        }
        float mean = s * (1.f / 256.f);
        float var  = s2 * (1.f / 256.f) - mean * mean;
        float rstd = rsqrtf(var + LN_EPS);
#pragma unroll
        for (int j = 0; j < 8; j++) {
            float v = (acc[t][j] - mean) * rstd;
            out[(tok0 + t) * ostride + col0 + j] = v * g[col0 + j] + bn[col0 + j];
        }
    }
}

// ============================================================
// Kernel 1: per 32 batch rows.
// h0 = h_dyn@W_dyn + b_dyn  (store)  ->  LN  ->  q = h@Wq + bq
// u[b,j,h] = sum_d Wk[j,64h+d]*q[64h+d] ;  qbk[b,h] = q_h . bk_h
// ============================================================
__global__ void __launch_bounds__(256, 1) k1(
    const float* __restrict__ h_dyn, const float* __restrict__ W_dyn,
    const float* __restrict__ b_dyn, const float* __restrict__ g_ndyn,
    const float* __restrict__ b_ndyn, const float* __restrict__ Wq,
    const float* __restrict__ bq, const float* __restrict__ Wk,
    const float* __restrict__ bk)
{
    extern __shared__ float sm[];
    float* sm_hd  = sm;                      // 32*512
    float* sm_h   = sm_hd + 32 * 512;        // 32*256
    float* sm_q   = sm_h  + 32 * 256;        // 32*256
    float* sm_wt  = sm_q  + 32 * 256;        // 16*260
    float* p_bdyn = sm_wt + 16 * WT_STRIDE;  // 5 x 256 params
    float* p_gn   = p_bdyn + 256;
    float* p_bn   = p_gn + 256;
    float* p_bq   = p_bn + 256;
    float* p_bk   = p_bq + 256;

    const int tid  = threadIdx.x;
    const int row0 = blockIdx.x * 32;

    {
        const float4* src = reinterpret_cast<const float4*>(h_dyn + (size_t)row0 * DDYN);
        for (int f = tid; f < 32 * 512 / 4; f += 256)
            reinterpret_cast<float4*>(sm_hd)[f] = src[f];
    }
    if (tid < 64) {
        reinterpret_cast<float4*>(p_bdyn)[tid] = reinterpret_cast<const float4*>(b_dyn)[tid];
        reinterpret_cast<float4*>(p_gn)[tid]   = reinterpret_cast<const float4*>(g_ndyn)[tid];
        reinterpret_cast<float4*>(p_bn)[tid]   = reinterpret_cast<const float4*>(b_ndyn)[tid];
        reinterpret_cast<float4*>(p_bq)[tid]   = reinterpret_cast<const float4*>(bq)[tid];
        reinterpret_cast<float4*>(p_bk)[tid]   = reinterpret_cast<const float4*>(bk)[tid];
    }
    __syncthreads();

    float acc[4][8];
    // ---- h0 = h_dyn @ W_dyn ----
    gemm_acc<256>(sm_hd, 512, 512, W_dyn, sm_wt, acc, tid);
    {
        const int tc = tid & 31, tok0 = (tid >> 5) * 4, col0 = tc * 8;
#pragma unroll
        for (int t = 0; t < 4; t++) {
            float s = 0.f, s2 = 0.f;
#pragma unroll
            for (int j = 0; j < 8; j++) {
                float v = acc[t][j] + p_bdyn[col0 + j];
                acc[t][j] = v; s += v; s2 += v * v;
            }
            float* h0p = g_h0 + (size_t)(row0 + tok0 + t) * DM + col0;
            reinterpret_cast<float4*>(h0p)[0] = make_float4(acc[t][0], acc[t][1], acc[t][2], acc[t][3]);
            reinterpret_cast<float4*>(h0p)[1] = make_float4(acc[t][4], acc[t][5], acc[t][6], acc[t][7]);
#pragma unroll
            for (int off = 16; off; off >>= 1) {
                s  += __shfl_xor_sync(0xffffffffu, s,  off);
                s2 += __shfl_xor_sync(0xffffffffu, s2, off);
            }
            float mean = s * (1.f / 256.f);
            float var  = s2 * (1.f / 256.f) - mean * mean;
            float rstd = rsqrtf(var + LN_EPS);
#pragma unroll
            for (int j = 0; j < 8; j++)
                sm_h[(tok0 + t) * DM + col0 + j] =
                    (acc[t][j] - mean) * rstd * p_gn[col0 + j] + p_bn[col0 + j];
        }
    }
    __syncthreads();

    // ---- q = h_ln @ Wq + bq ----
    gemm_acc<256>(sm_h, 256, 256, Wq, sm_wt, acc, tid);
    {
        const int tc = tid & 31, tok0 = (tid >> 5) * 4, col0 = tc * 8;
#pragma unroll
        for (int t = 0; t < 4; t++)
#pragma unroll
            for (int j = 0; j < 8; j++)
                sm_q[(tok0 + t) * DM + col0 + j] = acc[t][j] + p_bq[col0 + j];
    }
    __syncthreads();

    // ---- u[b,j,h] via staged Wk tiles ----
    for (int jt = 0; jt < 16; jt++) {
        const float4* src = reinterpret_cast<const float4*>(Wk + jt * 16 * DM);
        for (int f = tid; f < 1024; f += 256) {
            int r = f >> 6, c4 = f & 63;
            *reinterpret_cast<float4*>(sm_wt + r * WT_STRIDE + c4 * 4) = src[f];
        }
        __syncthreads();
        const int jl = tid & 15;
#pragma unroll
        for (int rr = 0; rr < 2; rr++) {
            const int r = (tid >> 4) + rr * 16;
            float ua[4];
#pragma unroll
            for (int h = 0; h < 4; h++) {
                float a = 0.f;
#pragma unroll
                for (int d4 = 0; d4 < 16; d4++) {
                    float4 qv = *reinterpret_cast<const float4*>(sm_q + r * DM + h * 64 + d4 * 4);
                    float4 wv = *reinterpret_cast<const float4*>(sm_wt + jl * WT_STRIDE + h * 64 + d4 * 4);
                    a += qv.x * wv.x + qv.y * wv.y + qv.z * wv.z + qv.w * wv.w;
                }
                ua[h] = a;
            }
            *reinterpret_cast<float4*>(g_u + (size_t)(row0 + r) * (DM * NH) + (jt * 16 + jl) * 4) =
                make_float4(ua[0], ua[1], ua[2], ua[3]);
        }
        __syncthreads();
    }

    // ---- qbk[b,h] ----
    if (tid < 128) {
        const int r = tid >> 2, h = tid & 3;
        float a = 0.f;
#pragma unroll
        for (int d = 0; d < 64; d++)
            a += sm_q[r * DM + h * 64 + d] * p_bk[h * 64 + d];
        g_qbk[(size_t)(row0 + r) * 4 + h] = a;
    }
}

// ============================================================
// Kernel 2: one block per batch row b. Full fused token path.
// ============================================================
__global__ void __launch_bounds__(512, 1) k2(
    const float* __restrict__ x_stat,
    const float* __restrict__ W_stat, const float* __restrict__ b_stat,
    const float* __restrict__ g_nstat, const float* __restrict__ b_nstat,
    const float* __restrict__ Wv, const float* __restrict__ bv,
    const float* __restrict__ g_mlp, const float* __restrict__ b_mlp,
    const float* __restrict__ W1, const float* __restrict__ b1,
    const float* __restrict__ W2, const float* __restrict__ b2,
    const float* __restrict__ Wo, const float* __restrict__ bo,
    const float* __restrict__ res_scale_p,
    float* __restrict__ out)
{
    extern __shared__ float sm[];
    float* A    = sm;                      // 64*260
    float* Bb   = A   + 64 * AST;          // 64*260
    float* xs   = Bb  + 64 * AST;          // 64*64
    float* Wt   = xs  + 64 * 64;           // 16*260
    float* us   = Wt  + 16 * WT_STRIDE;    // 1024 : u[j*4+h]
    float* pb   = us  + 1024;              // 10*256 params (see order below)
    float* wsm  = pb  + 10 * 256;          // 256 : w[h*64+k]
    float* zsm  = wsm + 256;               // 256
    float* ssum = zsm + 256;               // 8
    float* qbks = ssum + 8;                // 8

    const int tid = threadIdx.x;
    const int b   = blockIdx.x;

    // ---- cooperative loads ----
    {
        const float4* src = reinterpret_cast<const float4*>(x_stat + (size_t)b * 64 * 64);
        for (int f = tid; f < 1024; f += 512) reinterpret_cast<float4*>(xs)[f] = src[f];
        if (tid < 256)
            reinterpret_cast<float4*>(us)[tid] =
                reinterpret_cast<const float4*>(g_u + (size_t)b * 1024)[tid];
        if (tid < 64) {
            reinterpret_cast<float4*>(pb + 0 * 256)[tid] = reinterpret_cast<const float4*>(b_stat)[tid];
            reinterpret_cast<float4*>(pb + 1 * 256)[tid] = reinterpret_cast<const float4*>(g_nstat)[tid];
            reinterpret_cast<float4*>(pb + 2 * 256)[tid] = reinterpret_cast<const float4*>(b_nstat)[tid];
            reinterpret_cast<float4*>(pb + 3 * 256)[tid] = reinterpret_cast<const float4*>(bv)[tid];
            reinterpret_cast<float4*>(pb + 4 * 256)[tid] = reinterpret_cast<const float4*>(g_mlp)[tid];
            reinterpret_cast<float4*>(pb + 5 * 256)[tid] = reinterpret_cast<const float4*>(b_mlp)[tid];
            reinterpret_cast<float4*>(pb + 6 * 256)[tid] = reinterpret_cast<const float4*>(b1)[tid];
            reinterpret_cast<float4*>(pb + 7 * 256)[tid] = reinterpret_cast<const float4*>(b2)[tid];
            reinterpret_cast<float4*>(pb + 8 * 256)[tid] = reinterpret_cast<const float4*>(bo)[tid];
            reinterpret_cast<float4*>(pb + 9 * 256)[tid] =
                reinterpret_cast<const float4*>(g_h0 + (size_t)b * 256)[tid];
        }
        if (tid < 4) qbks[tid] = g_qbk[(size_t)b * 4 + tid];
    }
    __syncthreads();

    float acc[4][8];

    // ---- S1: s = x_stat @ W_stat + b_stat ; LN -> A ----
    gemm_acc<512>(xs, 64, 64, W_stat, Wt, acc, tid);
    epi_ln(acc, pb + 0 * 256, pb + 1 * 256, pb + 2 * 256, A, AST, tid);
    __syncthreads();

    // ---- logits / sigmoid / normalize / w_mean ----
    if (tid < 256) {
        const int k = tid >> 2, h = tid & 3;
        float a = qbks[h];
        const float* ar = A + k * AST;
#pragma unroll 4
        for (int j = 0; j < 256; j++) a += ar[j] * us[j * 4 + h];
        float lg = a * SCALE;
        wsm[h * 64 + k] = 1.f / (1.f + expf(-lg));
    }
    __syncthreads();
    if (tid < 4) {
        float s = 0.f;
        for (int k = 0; k < 64; k++) s += wsm[tid * 64 + k];
        ssum[tid] = s + 1e-6f;
    }
    __syncthreads();
    if (tid < 256) wsm[tid] = wsm[tid] / ssum[tid >> 6];
    __syncthreads();
    if (tid < 64)
        out[(size_t)B_ROWS * DM + (size_t)b * 64 + tid] =
            0.25f * (wsm[tid] + wsm[64 + tid] + wsm[128 + tid] + wsm[192 + tid]);

    // ---- S2: v = A @ Wv + bv ; LN(g_mlp) -> Bb ----
    gemm_acc<512>(A, AST, 256, Wv, Wt, acc, tid);
    epi_ln(acc, pb + 3 * 256, pb + 4 * 256, pb + 5 * 256, Bb, AST, tid);
    __syncthreads();

    // ---- S3: t = gelu(Bb @ W1 + b1) -> A ----
    gemm_acc<512>(Bb, AST, 256, W1, Wt, acc, tid);
    {
        const int tc = tid & 31, tok0 = (tid >> 5) * 4, col0 = tc * 8;
#pragma unroll
        for (int t = 0; t < 4; t++)
#pragma unroll
            for (int j = 0; j < 8; j++) {
                float x = acc[t][j] + pb[6 * 256 + col0 + j];
                A[(tok0 + t) * AST + col0 + j] = 0.5f * x * (1.f + erff(x * 0.70710678118f));
            }
    }
    __syncthreads();

    // ---- S4: vtok = A @ W2 + b2 -> Bb ----
    gemm_acc<512>(A, AST, 256, W2, Wt, acc, tid);
    {
        const int tc = tid & 31, tok0 = (tid >> 5) * 4, col0 = tc * 8;
#pragma unroll
        for (int t = 0; t < 4; t++)
#pragma unroll
            for (int j = 0; j < 8; j++)
                Bb[(tok0 + t) * AST + col0 + j] = acc[t][j] + pb[7 * 256 + col0 + j];
    }
    __syncthreads();

    // ---- z[d] = sum_k w[h(d),k] * vtok[k,d] ----
    if (tid < 256) {
        const int d = tid, h = d >> 6;
        float a = 0.f;
        const float* wr = wsm + h * 64;
#pragma unroll 8
        for (int k = 0; k < 64; k++) a += wr[k] * Bb[k * AST + d];
        zsm[d] = a;
    }
    __syncthreads();

    // ---- c = z @ Wo + bo ; out = h0 + res_scale*c ----
    if (tid < 256) {
        const int d = tid;
        float a = 0.f;
#pragma unroll 8
        for (int i = 0; i < 256; i++) a += zsm[i] * Wo[i * DM + d];
        float rs = *res_scale_p;
        out[(size_t)b * DM + d] = pb[9 * 256 + d] + rs * (a + pb[8 * 256 + d]);
    }
}

// ============================================================
extern "C" void kernel_launch(void* const* d_in, const int* in_sizes, int n_in,
                              void* d_out, int out_size)
{
    const float* h_dyn   = (const float*)d_in[0];
    const float* x_stat  = (const float*)d_in[1];
    const float* W_dyn   = (const float*)d_in[2];
    const float* b_dyn   = (const float*)d_in[3];
    const float* W_stat  = (const float*)d_in[4];
    const float* b_stat  = (const float*)d_in[5];
    const float* g_ndyn  = (const float*)d_in[6];
    const float* b_ndyn  = (const float*)d_in[7];
    const float* g_nstat = (const float*)d_in[8];
    const float* b_nstat = (const float*)d_in[9];
    const float* Wq      = (const float*)d_in[10];
    const float* bq      = (const float*)d_in[11];
    const float* Wk      = (const float*)d_in[12];
    const float* bk      = (const float*)d_in[13];
    const float* Wv      = (const float*)d_in[14];
    const float* bv      = (const float*)d_in[15];
    const float* g_mlp   = (const float*)d_in[16];
    const float* b_mlp   = (const float*)d_in[17];
    const float* W1      = (const float*)d_in[18];
    const float* b1      = (const float*)d_in[19];
    const float* W2      = (const float*)d_in[20];
    const float* b2      = (const float*)d_in[21];
    const float* Wo      = (const float*)d_in[22];
    const float* bo      = (const float*)d_in[23];
    const float* res_sc  = (const float*)d_in[24];
    float* out = (float*)d_out;

    const int SMEM1 = (32 * 512 + 32 * 256 + 32 * 256 + 16 * WT_STRIDE + 5 * 256) * 4;
    const int SMEM2 = (64 * AST * 2 + 64 * 64 + 16 * WT_STRIDE + 1024 + 10 * 256 + 256 + 256 + 16) * 4;

    cudaFuncSetAttribute(k1, cudaFuncAttributeMaxDynamicSharedMemorySize, SMEM1);
    cudaFuncSetAttribute(k2, cudaFuncAttributeMaxDynamicSharedMemorySize, SMEM2);

    k1<<<B_ROWS / 32, 256, SMEM1>>>(h_dyn, W_dyn, b_dyn, g_ndyn, b_ndyn, Wq, bq, Wk, bk);
    k2<<<B_ROWS, 512, SMEM2>>>(x_stat, W_stat, b_stat, g_nstat, b_nstat,
                               Wv, bv, g_mlp, b_mlp, W1, b1, W2, b2, Wo, bo,
                               res_sc, out);
}

// round 4
// speedup vs baseline: 1.0008x; 1.0008x over previous
#include <cuda_runtime.h>
#include <math.h>

#define B_ROWS 4096
#define KTOK   64
#define DM     256
#define DDYN   512
#define NH     4
#define SCALE  0.125f
#define LN_EPS 1e-5f
#define WT_STRIDE 260   // padded smem stride for weight tiles
#define AST       260   // padded smem stride for activation tiles

// ---- scratch (allocation-free rule: __device__ globals) ----
__device__ float g_h0 [B_ROWS * DM];        // 4 MB
__device__ float g_u  [B_ROWS * DM * NH];   // 16 MB : u[b][j][h]
__device__ float g_qbk[B_ROWS * NH];        // 64 KB

// ============================================================
// Shared-memory tiled GEMM: C[rows,256] = Asm[rows,kdim] @ Wg[kdim,256]
// Thread tile 4 tokens x 8 cols. rows = 4 * (blockDim/32).
// Weight rows streamed through 16x256 smem tile (padded stride).
// ============================================================
template<int NTHREADS>
__device__ __forceinline__ void gemm_acc(
    const float* __restrict__ Asm, int astride, int kdim,
    const float* __restrict__ Wg, float* __restrict__ Wt,
    float acc[4][8], int tid)
{
#pragma unroll
    for (int t = 0; t < 4; t++)
#pragma unroll
        for (int j = 0; j < 8; j++) acc[t][j] = 0.f;

    const int tc   = tid & 31;
    const int tok0 = (tid >> 5) * 4;
    const int col0 = tc * 8;
    const int nkt  = kdim >> 4;

    for (int kt = 0; kt < nkt; ++kt) {
        // stage 16 weight rows (16x256 floats) into smem, coalesced
        const float4* src = reinterpret_cast<const float4*>(Wg + kt * 16 * DM);
#pragma unroll
        for (int f = tid; f < 1024; f += NTHREADS) {
            int row = f >> 6, c4 = f & 63;
            float4 v = src[f];
            *reinterpret_cast<float4*>(Wt + row * WT_STRIDE + c4 * 4) = v;
        }
        __syncthreads();
#pragma unroll
        for (int kk4 = 0; kk4 < 4; ++kk4) {
            const int kbase = kt * 16 + kk4 * 4;
            float a_[4][4];
#pragma unroll
            for (int t = 0; t < 4; t++) {
                float4 v = *reinterpret_cast<const float4*>(Asm + (tok0 + t) * astride + kbase);
                a_[t][0] = v.x; a_[t][1] = v.y; a_[t][2] = v.z; a_[t][3] = v.w;
            }
#pragma unroll
            for (int r = 0; r < 4; r++) {
                const float4 w0 = *reinterpret_cast<const float4*>(Wt + (kk4 * 4 + r) * WT_STRIDE + col0);
                const float4 w1 = *reinterpret_cast<const float4*>(Wt + (kk4 * 4 + r) * WT_STRIDE + col0 + 4);
                float w[8] = {w0.x, w0.y, w0.z, w0.w, w1.x, w1.y, w1.z, w1.w};
#pragma unroll
                for (int t = 0; t < 4; t++) {
                    const float a = a_[t][r];
#pragma unroll
                    for (int j = 0; j < 8; j++)
                        acc[t][j] = fmaf(a, w[j], acc[t][j]);
                }
            }
        }
        __syncthreads();
    }
}

// epilogue: add bias, LayerNorm per token row, write to smem (strided)
__device__ __forceinline__ void epi_ln(
    float acc[4][8], const float* __restrict__ bias,
    const float* __restrict__ g, const float* __restrict__ bn,
    float* __restrict__ out, int ostride, int tid)
{
    const int tc = tid & 31, tok0 = (tid >> 5) * 4, col0 = tc * 8;
#pragma unroll
    for (int t = 0; t < 4; t++) {
        float s = 0.f, s2 = 0.f;
#pragma unroll
        for (int j = 0; j < 8; j++) {
            float v = acc[t][j] + bias[col0 + j];
            acc[t][j] = v; s += v; s2 += v * v;
        }
#pragma unroll
        for (int off = 16; off; off >>= 1) {
            s  += __shfl_xor_sync(0xffffffffu, s,  off);
            s2 += __shfl_xor_sync(0xffffffffu, s2, off);
        }
        float mean = s * (1.f / 256.f);
        float var  = s2 * (1.f / 256.f) - mean * mean;
        float rstd = rsqrtf(var + LN_EPS);
#pragma unroll
        for (int j = 0; j < 8; j++) {
            float v = (acc[t][j] - mean) * rstd;
            out[(tok0 + t) * ostride + col0 + j] = v * g[col0 + j] + bn[col0 + j];
        }
    }
}

// ============================================================
// Kernel 1: per 32 batch rows.
// h0 = h_dyn@W_dyn + b_dyn  (store)  ->  LN  ->  q = h@Wq + bq
// u[b,j,h] = sum_d Wk[j,64h+d]*q[64h+d] ;  qbk[b,h] = q_h . bk_h
// ============================================================
__global__ void __launch_bounds__(256, 1) k1(
    const float* __restrict__ h_dyn, const float* __restrict__ W_dyn,
    const float* __restrict__ b_dyn, const float* __restrict__ g_ndyn,
    const float* __restrict__ b_ndyn, const float* __restrict__ Wq,
    const float* __restrict__ bq, const float* __restrict__ Wk,
    const float* __restrict__ bk)
{
    extern __shared__ float sm[];
    float* sm_hd  = sm;                      // 32*512
    float* sm_h   = sm_hd + 32 * 512;        // 32*256
    float* sm_q   = sm_h  + 32 * 256;        // 32*256
    float* sm_wt  = sm_q  + 32 * 256;        // 16*260
    float* p_bdyn = sm_wt + 16 * WT_STRIDE;  // 5 x 256 params
    float* p_gn   = p_bdyn + 256;
    float* p_bn   = p_gn + 256;
    float* p_bq   = p_bn + 256;
    float* p_bk   = p_bq + 256;

    const int tid  = threadIdx.x;
    const int row0 = blockIdx.x * 32;

    {
        const float4* src = reinterpret_cast<const float4*>(h_dyn + (size_t)row0 * DDYN);
        for (int f = tid; f < 32 * 512 / 4; f += 256)
            reinterpret_cast<float4*>(sm_hd)[f] = src[f];
    }
    if (tid < 64) {
        reinterpret_cast<float4*>(p_bdyn)[tid] = reinterpret_cast<const float4*>(b_dyn)[tid];
        reinterpret_cast<float4*>(p_gn)[tid]   = reinterpret_cast<const float4*>(g_ndyn)[tid];
        reinterpret_cast<float4*>(p_bn)[tid]   = reinterpret_cast<const float4*>(b_ndyn)[tid];
        reinterpret_cast<float4*>(p_bq)[tid]   = reinterpret_cast<const float4*>(bq)[tid];
        reinterpret_cast<float4*>(p_bk)[tid]   = reinterpret_cast<const float4*>(bk)[tid];
    }
    __syncthreads();

    float acc[4][8];
    // ---- h0 = h_dyn @ W_dyn ----
    gemm_acc<256>(sm_hd, 512, 512, W_dyn, sm_wt, acc, tid);
    {
        const int tc = tid & 31, tok0 = (tid >> 5) * 4, col0 = tc * 8;
#pragma unroll
        for (int t = 0; t < 4; t++) {
            float s = 0.f, s2 = 0.f;
#pragma unroll
            for (int j = 0; j < 8; j++) {
                float v = acc[t][j] + p_bdyn[col0 + j];
                acc[t][j] = v; s += v; s2 += v * v;
            }
            float* h0p = g_h0 + (size_t)(row0 + tok0 + t) * DM + col0;
            reinterpret_cast<float4*>(h0p)[0] = make_float4(acc[t][0], acc[t][1], acc[t][2], acc[t][3]);
            reinterpret_cast<float4*>(h0p)[1] = make_float4(acc[t][4], acc[t][5], acc[t][6], acc[t][7]);
#pragma unroll
            for (int off = 16; off; off >>= 1) {
                s  += __shfl_xor_sync(0xffffffffu, s,  off);
                s2 += __shfl_xor_sync(0xffffffffu, s2, off);
            }
            float mean = s * (1.f / 256.f);
            float var  = s2 * (1.f / 256.f) - mean * mean;
            float rstd = rsqrtf(var + LN_EPS);
#pragma unroll
            for (int j = 0; j < 8; j++)
                sm_h[(tok0 + t) * DM + col0 + j] =
                    (acc[t][j] - mean) * rstd * p_gn[col0 + j] + p_bn[col0 + j];
        }
    }
    __syncthreads();

    // ---- q = h_ln @ Wq + bq ----
    gemm_acc<256>(sm_h, 256, 256, Wq, sm_wt, acc, tid);
    {
        const int tc = tid & 31, tok0 = (tid >> 5) * 4, col0 = tc * 8;
#pragma unroll
        for (int t = 0; t < 4; t++)
#pragma unroll
            for (int j = 0; j < 8; j++)
                sm_q[(tok0 + t) * DM + col0 + j] = acc[t][j] + p_bq[col0 + j];
    }
    __syncthreads();

    // ---- u[b,j,h] via staged Wk tiles ----
    for (int jt = 0; jt < 16; jt++) {
        const float4* src = reinterpret_cast<const float4*>(Wk + jt * 16 * DM);
        for (int f = tid; f < 1024; f += 256) {
            int r = f >> 6, c4 = f & 63;
            *reinterpret_cast<float4*>(sm_wt + r * WT_STRIDE + c4 * 4) = src[f];
        }
        __syncthreads();
        const int jl = tid & 15;
#pragma unroll
        for (int rr = 0; rr < 2; rr++) {
            const int r = (tid >> 4) + rr * 16;
            float ua[4];
#pragma unroll
            for (int h = 0; h < 4; h++) {
                float a = 0.f;
#pragma unroll
                for (int d4 = 0; d4 < 16; d4++) {
                    float4 qv = *reinterpret_cast<const float4*>(sm_q + r * DM + h * 64 + d4 * 4);
                    float4 wv = *reinterpret_cast<const float4*>(sm_wt + jl * WT_STRIDE + h * 64 + d4 * 4);
                    a += qv.x * wv.x + qv.y * wv.y + qv.z * wv.z + qv.w * wv.w;
                }
                ua[h] = a;
            }
            *reinterpret_cast<float4*>(g_u + (size_t)(row0 + r) * (DM * NH) + (jt * 16 + jl) * 4) =
                make_float4(ua[0], ua[1], ua[2], ua[3]);
        }
        __syncthreads();
    }

    // ---- qbk[b,h] ----
    if (tid < 128) {
        const int r = tid >> 2, h = tid & 3;
        float a = 0.f;
#pragma unroll
        for (int d = 0; d < 64; d++)
            a += sm_q[r * DM + h * 64 + d] * p_bk[h * 64 + d];
        g_qbk[(size_t)(row0 + r) * 4 + h] = a;
    }
}

// ============================================================
// Kernel 2: one block per batch row b. Full fused token path.
// ============================================================
__global__ void __launch_bounds__(512, 1) k2(
    const float* __restrict__ x_stat,
    const float* __restrict__ W_stat, const float* __restrict__ b_stat,
    const float* __restrict__ g_nstat, const float* __restrict__ b_nstat,
    const float* __restrict__ Wv, const float* __restrict__ bv,
    const float* __restrict__ g_mlp, const float* __restrict__ b_mlp,
    const float* __restrict__ W1, const float* __restrict__ b1,
    const float* __restrict__ W2, const float* __restrict__ b2,
    const float* __restrict__ Wo, const float* __restrict__ bo,
    const float* __restrict__ res_scale_p,
    float* __restrict__ out)
{
    extern __shared__ float sm[];
    float* A    = sm;                      // 64*260
    float* Bb   = A   + 64 * AST;          // 64*260
    float* xs   = Bb  + 64 * AST;          // 64*64
    float* Wt   = xs  + 64 * 64;           // 16*260
    float* us   = Wt  + 16 * WT_STRIDE;    // 1024 : u[j*4+h]
    float* pb   = us  + 1024;              // 10*256 params (see order below)
    float* wsm  = pb  + 10 * 256;          // 256 : w[h*64+k]
    float* zsm  = wsm + 256;               // 256
    float* ssum = zsm + 256;               // 8
    float* qbks = ssum + 8;                // 8

    const int tid = threadIdx.x;
    const int b   = blockIdx.x;

    // ---- cooperative loads ----
    {
        const float4* src = reinterpret_cast<const float4*>(x_stat + (size_t)b * 64 * 64);
        for (int f = tid; f < 1024; f += 512) reinterpret_cast<float4*>(xs)[f] = src[f];
        if (tid < 256)
            reinterpret_cast<float4*>(us)[tid] =
                reinterpret_cast<const float4*>(g_u + (size_t)b * 1024)[tid];
        if (tid < 64) {
            reinterpret_cast<float4*>(pb + 0 * 256)[tid] = reinterpret_cast<const float4*>(b_stat)[tid];
            reinterpret_cast<float4*>(pb + 1 * 256)[tid] = reinterpret_cast<const float4*>(g_nstat)[tid];
            reinterpret_cast<float4*>(pb + 2 * 256)[tid] = reinterpret_cast<const float4*>(b_nstat)[tid];
            reinterpret_cast<float4*>(pb + 3 * 256)[tid] = reinterpret_cast<const float4*>(bv)[tid];
            reinterpret_cast<float4*>(pb + 4 * 256)[tid] = reinterpret_cast<const float4*>(g_mlp)[tid];
            reinterpret_cast<float4*>(pb + 5 * 256)[tid] = reinterpret_cast<const float4*>(b_mlp)[tid];
            reinterpret_cast<float4*>(pb + 6 * 256)[tid] = reinterpret_cast<const float4*>(b1)[tid];
            reinterpret_cast<float4*>(pb + 7 * 256)[tid] = reinterpret_cast<const float4*>(b2)[tid];
            reinterpret_cast<float4*>(pb + 8 * 256)[tid] = reinterpret_cast<const float4*>(bo)[tid];
            reinterpret_cast<float4*>(pb + 9 * 256)[tid] =
                reinterpret_cast<const float4*>(g_h0 + (size_t)b * 256)[tid];
        }
        if (tid < 4) qbks[tid] = g_qbk[(size_t)b * 4 + tid];
    }
    __syncthreads();

    float acc[4][8];

    // ---- S1: s = x_stat @ W_stat + b_stat ; LN -> A ----
    gemm_acc<512>(xs, 64, 64, W_stat, Wt, acc, tid);
    epi_ln(acc, pb + 0 * 256, pb + 1 * 256, pb + 2 * 256, A, AST, tid);
    __syncthreads();

    // ---- logits / sigmoid / normalize / w_mean ----
    if (tid < 256) {
        const int k = tid >> 2, h = tid & 3;
        float a = qbks[h];
        const float* ar = A + k * AST;
#pragma unroll 4
        for (int j = 0; j < 256; j++) a += ar[j] * us[j * 4 + h];
        float lg = a * SCALE;
        wsm[h * 64 + k] = 1.f / (1.f + expf(-lg));
    }
    __syncthreads();
    if (tid < 4) {
        float s = 0.f;
        for (int k = 0; k < 64; k++) s += wsm[tid * 64 + k];
        ssum[tid] = s + 1e-6f;
    }
    __syncthreads();
    if (tid < 256) wsm[tid] = wsm[tid] / ssum[tid >> 6];
    __syncthreads();
    if (tid < 64)
        out[(size_t)B_ROWS * DM + (size_t)b * 64 + tid] =
            0.25f * (wsm[tid] + wsm[64 + tid] + wsm[128 + tid] + wsm[192 + tid]);

    // ---- S2: v = A @ Wv + bv ; LN(g_mlp) -> Bb ----
    gemm_acc<512>(A, AST, 256, Wv, Wt, acc, tid);
    epi_ln(acc, pb + 3 * 256, pb + 4 * 256, pb + 5 * 256, Bb, AST, tid);
    __syncthreads();

    // ---- S3: t = gelu(Bb @ W1 + b1) -> A ----
    gemm_acc<512>(Bb, AST, 256, W1, Wt, acc, tid);
    {
        const int tc = tid & 31, tok0 = (tid >> 5) * 4, col0 = tc * 8;
#pragma unroll
        for (int t = 0; t < 4; t++)
#pragma unroll
            for (int j = 0; j < 8; j++) {
                float x = acc[t][j] + pb[6 * 256 + col0 + j];
                A[(tok0 + t) * AST + col0 + j] = 0.5f * x * (1.f + erff(x * 0.70710678118f));
            }
    }
    __syncthreads();

    // ---- S4: vtok = A @ W2 + b2 -> Bb ----
    gemm_acc<512>(A, AST, 256, W2, Wt, acc, tid);
    {
        const int tc = tid & 31, tok0 = (tid >> 5) * 4, col0 = tc * 8;
#pragma unroll
        for (int t = 0; t < 4; t++)
#pragma unroll
            for (int j = 0; j < 8; j++)
                Bb[(tok0 + t) * AST + col0 + j] = acc[t][j] + pb[7 * 256 + col0 + j];
    }
    __syncthreads();

    // ---- z[d] = sum_k w[h(d),k] * vtok[k,d] ----
    if (tid < 256) {
        const int d = tid, h = d >> 6;
        float a = 0.f;
        const float* wr = wsm + h * 64;
#pragma unroll 8
        for (int k = 0; k < 64; k++) a += wr[k] * Bb[k * AST + d];
        zsm[d] = a;
    }
    __syncthreads();

    // ---- c = z @ Wo + bo ; out = h0 + res_scale*c ----
    if (tid < 256) {
        const int d = tid;
        float a = 0.f;
#pragma unroll 8
        for (int i = 0; i < 256; i++) a += zsm[i] * Wo[i * DM + d];
        float rs = *res_scale_p;
        out[(size_t)b * DM + d] = pb[9 * 256 + d] + rs * (a + pb[8 * 256 + d]);
    }
}

// ============================================================
extern "C" void kernel_launch(void* const* d_in, const int* in_sizes, int n_in,
                              void* d_out, int out_size)
{
    const float* h_dyn   = (const float*)d_in[0];
    const float* x_stat  = (const float*)d_in[1];
    const float* W_dyn   = (const float*)d_in[2];
    const float* b_dyn   = (const float*)d_in[3];
    const float* W_stat  = (const float*)d_in[4];
    const float* b_stat  = (const float*)d_in[5];
    const float* g_ndyn  = (const float*)d_in[6];
    const float* b_ndyn  = (const float*)d_in[7];
    const float* g_nstat = (const float*)d_in[8];
    const float* b_nstat = (const float*)d_in[9];
    const float* Wq      = (const float*)d_in[10];
    const float* bq      = (const float*)d_in[11];
    const float* Wk      = (const float*)d_in[12];
    const float* bk      = (const float*)d_in[13];
    const float* Wv      = (const float*)d_in[14];
    const float* bv      = (const float*)d_in[15];
    const float* g_mlp   = (const float*)d_in[16];
    const float* b_mlp   = (const float*)d_in[17];
    const float* W1      = (const float*)d_in[18];
    const float* b1      = (const float*)d_in[19];
    const float* W2      = (const float*)d_in[20];
    const float* b2      = (const float*)d_in[21];
    const float* Wo      = (const float*)d_in[22];
    const float* bo      = (const float*)d_in[23];
    const float* res_sc  = (const float*)d_in[24];
    float* out = (float*)d_out;

    const int SMEM1 = (32 * 512 + 32 * 256 + 32 * 256 + 16 * WT_STRIDE + 5 * 256) * 4;
    const int SMEM2 = (64 * AST * 2 + 64 * 64 + 16 * WT_STRIDE + 1024 + 10 * 256 + 256 + 256 + 16) * 4;

    cudaFuncSetAttribute(k1, cudaFuncAttributeMaxDynamicSharedMemorySize, SMEM1);
    cudaFuncSetAttribute(k2, cudaFuncAttributeMaxDynamicSharedMemorySize, SMEM2);

    k1<<<B_ROWS / 32, 256, SMEM1>>>(h_dyn, W_dyn, b_dyn, g_ndyn, b_ndyn, Wq, bq, Wk, bk);
    k2<<<B_ROWS, 512, SMEM2>>>(x_stat, W_stat, b_stat, g_nstat, b_nstat,
                               Wv, bv, g_mlp, b_mlp, W1, b1, W2, b2, Wo, bo,
                               res_sc, out);
}